// round 6
// baseline (speedup 1.0000x reference)
#include <cuda_runtime.h>
#include <cuda_bf16.h>
#include <cstdint>
#include <cstring>

// ============================================================================
// SumConv, single fused kernel (HMMA mma.sync, compute_103-safe).
//   out[b,f,co] = log( sum_ci exp(ll[b,f,ci]) * softmax_ci(logits)[co,ci,kh,kw] )
// Grid 512 = 16 groups x 32 M-tiles(32 rows), 256 threads.
// Leader CTA per group (tile==0) computes softmax weights -> pre-swizzled
// bf16 hi/lo image (SMEM + g_wimg gmem), releases g_flag[g]; followers overlap
// their E-phase, acquire-spin, copy image from L2. 3-term bf16 split GEMM
// (Eh*Wh + Eh*Wl + El*Wh) in fp32 accum, then log + store.
// All 512 CTAs are co-resident (>=4 CTAs/SM by regs+smem), so spin is safe.
// Replays see g_flag==1 with g_wimg already holding identical bytes: benign.
// ============================================================================

#define SWZ(x) ((x) ^ (((x) >> 3) & 0x70))

__device__ __forceinline__ uint32_t smem_u32(const void* p) {
    uint32_t a;
    asm("{ .reg .u64 t; cvta.to.shared.u64 t, %1; cvt.u32.u64 %0, t; }" : "=r"(a) : "l"(p));
    return a;
}

#define LDSM_X4(r0, r1, r2, r3, addr) \
    asm volatile("ldmatrix.sync.aligned.m8n8.x4.shared.b16 {%0,%1,%2,%3}, [%4];" \
        : "=r"(r0), "=r"(r1), "=r"(r2), "=r"(r3) : "r"(addr))

#define MMA_BF16(D, A, B0, B1) \
    asm volatile("mma.sync.aligned.m16n8k16.row.col.f32.bf16.bf16.f32 " \
        "{%0,%1,%2,%3}, {%4,%5,%6,%7}, {%8,%9}, {%0,%1,%2,%3};" \
        : "+f"(D[0]), "+f"(D[1]), "+f"(D[2]), "+f"(D[3]) \
        : "r"(A[0]), "r"(A[1]), "r"(A[2]), "r"(A[3]), "r"(B0), "r"(B1))

// Pre-swizzled weight images: per group, [0,8K) = Wh, [8K,16K) = Wl.
__device__ __align__(16) unsigned char g_wimg[16][16384];
__device__ int g_flag[16];   // zero-initialized at module load

static constexpr int S_AH = 0;
static constexpr int S_AL = 4096;
static constexpr int S_BH = 8192;
static constexpr int S_BL = 16384;

__global__ __launch_bounds__(256) void sumconv_fused_kernel(
    const float* __restrict__ ll, const float* __restrict__ logits,
    float* __restrict__ out)
{
    __shared__ __align__(1024) unsigned char sm[24576];
    const uint32_t sa = smem_u32(sm);

    const int t   = threadIdx.x;
    const int wid = t >> 5;
    const int lid = t & 31;

    const int g    = blockIdx.x >> 5;    // group = kh*4 + kw
    const int tile = blockIdx.x & 31;    // 32-row M tile
    const int kh = g >> 2, kw = g & 3;
    const int fbase = kh * 32 + kw;

    // ---- Issue E loads (DRAM) up front, always ----
    float4 v[2];
    int er[2], ec4[2];
    #pragma unroll
    for (int i = 0; i < 2; i++) {
        int idx4 = t + 256 * i;          // 0..511
        int r    = idx4 >> 4;            // local row 0..31
        int c4   = (idx4 & 15) << 2;
        er[i] = r; ec4[i] = c4;
        int ridx = tile * 32 + r;
        int b    = ridx >> 6;
        int pos  = ridx & 63;
        int f    = ((pos >> 3) << 7) + ((pos & 7) << 2) + fbase;
        v[i] = *(const float4*)(ll + ((((b << 10) + f) << 6) + c4));
    }

    if (tile == 0) {
        // ================= LEADER: compute weights for this group =================
        // Warp scheme: warp covers co = wid*8+i, lanes cover ci = lid, lid+32.
        #pragma unroll
        for (int i = 0; i < 8; i++) {
            int co = wid * 8 + i;
            float x0 = logits[(co * 64 + lid) * 16 + g];
            float x1 = logits[(co * 64 + lid + 32) * 16 + g];
            float e0 = __expf(x0), e1 = __expf(x1);   // logits ~N(0,1): no max-sub needed
            float s = e0 + e1;
            #pragma unroll
            for (int off = 16; off; off >>= 1)
                s += __shfl_xor_sync(0xFFFFFFFFu, s, off);
            float inv = __frcp_rn(s);
            float w0 = e0 * inv, w1 = e1 * inv;

            __nv_bfloat16 h0 = __float2bfloat16(w0);
            __nv_bfloat16 h1 = __float2bfloat16(w1);
            __nv_bfloat16 l0 = __float2bfloat16(w0 - __bfloat162float(h0));
            __nv_bfloat16 l1 = __float2bfloat16(w1 - __bfloat162float(h1));

            uint32_t o0 = SWZ((uint32_t)(co * 128 + lid * 2));
            uint32_t o1 = SWZ((uint32_t)(co * 128 + (lid + 32) * 2));
            // own SMEM image
            *(__nv_bfloat16*)(sm + S_BH + o0) = h0;
            *(__nv_bfloat16*)(sm + S_BH + o1) = h1;
            *(__nv_bfloat16*)(sm + S_BL + o0) = l0;
            *(__nv_bfloat16*)(sm + S_BL + o1) = l1;
            // gmem image for followers
            *(__nv_bfloat16*)(g_wimg[g] + o0) = h0;
            *(__nv_bfloat16*)(g_wimg[g] + o1) = h1;
            *(__nv_bfloat16*)(g_wimg[g] + 8192 + o0) = l0;
            *(__nv_bfloat16*)(g_wimg[g] + 8192 + o1) = l1;
        }
        __threadfence();
        __syncthreads();
        if (t == 0)
            asm volatile("st.release.gpu.global.b32 [%0], %1;"
                         :: "l"(&g_flag[g]), "r"(1) : "memory");
    }

    // ---- Phase E: exp + bf16 hi/lo split -> swizzled A tiles (all CTAs) ----
    #pragma unroll
    for (int i = 0; i < 2; i++) {
        float e0 = __expf(v[i].x), e1 = __expf(v[i].y);
        float e2 = __expf(v[i].z), e3 = __expf(v[i].w);
        __nv_bfloat16 h0 = __float2bfloat16(e0), h1 = __float2bfloat16(e1);
        __nv_bfloat16 h2 = __float2bfloat16(e2), h3 = __float2bfloat16(e3);
        __nv_bfloat16 q0 = __float2bfloat16(e0 - __bfloat162float(h0));
        __nv_bfloat16 q1 = __float2bfloat16(e1 - __bfloat162float(h1));
        __nv_bfloat16 q2 = __float2bfloat16(e2 - __bfloat162float(h2));
        __nv_bfloat16 q3 = __float2bfloat16(e3 - __bfloat162float(h3));
        unsigned long long uh, ul;
        {
            unsigned short s0, s1, s2, s3;
            memcpy(&s0, &h0, 2); memcpy(&s1, &h1, 2); memcpy(&s2, &h2, 2); memcpy(&s3, &h3, 2);
            uh = (unsigned long long)s0 | ((unsigned long long)s1 << 16) |
                 ((unsigned long long)s2 << 32) | ((unsigned long long)s3 << 48);
            memcpy(&s0, &q0, 2); memcpy(&s1, &q1, 2); memcpy(&s2, &q2, 2); memcpy(&s3, &q3, 2);
            ul = (unsigned long long)s0 | ((unsigned long long)s1 << 16) |
                 ((unsigned long long)s2 << 32) | ((unsigned long long)s3 << 48);
        }
        uint32_t sw = SWZ((uint32_t)(er[i] * 128 + ec4[i] * 2));
        *(unsigned long long*)(sm + S_AH + sw) = uh;
        *(unsigned long long*)(sm + S_AL + sw) = ul;
    }

    if (tile != 0) {
        // ================= FOLLOWER: wait for weights, copy image =================
        if (lid == 0) {
            uint32_t f;
            do {
                asm volatile("ld.acquire.gpu.global.b32 %0, [%1];"
                             : "=r"(f) : "l"(&g_flag[g]) : "memory");
                if (!f) __nanosleep(64);
            } while (!f);
        }
        __syncwarp();
        #pragma unroll
        for (int i = 0; i < 4; i++) {
            float4 wv = *(const float4*)(g_wimg[g] + 16 * t + 4096 * i);
            *(float4*)(sm + S_BH + 16 * t + 4096 * i) = wv;
        }
    }

    __syncthreads();

    // ---- MMA: warp -> m16 (rows 16*(wid&1)) x n16 (cols 16*(wid>>1)) ----
    const int mrow  = 16 * (wid & 1);
    const int nbase = 16 * (wid >> 1);

    const uint32_t a_row = mrow + (lid & 7) + ((lid >> 3) & 1) * 8;
    const uint32_t a_kb  = ((lid >> 4) & 1) * 16;
    const uint32_t b_row = nbase + (lid & 7) + ((lid >> 4) & 1) * 8;
    const uint32_t b_kb  = ((lid >> 3) & 1) * 16;

    float acc[2][4];
    #pragma unroll
    for (int j = 0; j < 2; j++)
        #pragma unroll
        for (int q = 0; q < 4; q++) acc[j][q] = 0.0f;

    #pragma unroll
    for (int kc = 0; kc < 4; kc++) {
        uint32_t ah[4], al[4], bh[4], bl[4];
        uint32_t aoff = SWZ(a_row * 128 + kc * 32 + a_kb);
        uint32_t boff = SWZ(b_row * 128 + kc * 32 + b_kb);
        LDSM_X4(ah[0], ah[1], ah[2], ah[3], sa + S_AH + aoff);
        LDSM_X4(al[0], al[1], al[2], al[3], sa + S_AL + aoff);
        LDSM_X4(bh[0], bh[1], bh[2], bh[3], sa + S_BH + boff);
        LDSM_X4(bl[0], bl[1], bl[2], bl[3], sa + S_BL + boff);

        MMA_BF16(acc[0], ah, bh[0], bh[1]);
        MMA_BF16(acc[1], ah, bh[2], bh[3]);
        MMA_BF16(acc[0], al, bh[0], bh[1]);
        MMA_BF16(acc[1], al, bh[2], bh[3]);
        MMA_BF16(acc[0], ah, bl[0], bl[1]);
        MMA_BF16(acc[1], ah, bl[2], bl[3]);
    }

    // ---- Epilogue: log + store ----
    {
        int r0 = mrow + (lid >> 2);
        int r1 = r0 + 8;
        int cb = nbase + 2 * (lid & 3);

        int ridx0 = tile * 32 + r0;
        int b0 = ridx0 >> 6, p0 = ridx0 & 63;
        int f0 = ((p0 >> 3) << 7) + ((p0 & 7) << 2) + fbase;
        float* ob0 = out + ((((b0 << 10) + f0) << 6) + cb);

        int ridx1 = tile * 32 + r1;
        int b1 = ridx1 >> 6, p1 = ridx1 & 63;
        int f1 = ((p1 >> 3) << 7) + ((p1 & 7) << 2) + fbase;
        float* ob1 = out + ((((b1 << 10) + f1) << 6) + cb);

        #pragma unroll
        for (int j = 0; j < 2; j++) {
            float2 o0, o1;
            o0.x = __logf(acc[j][0]);
            o0.y = __logf(acc[j][1]);
            o1.x = __logf(acc[j][2]);
            o1.y = __logf(acc[j][3]);
            *(float2*)(ob0 + 8 * j) = o0;
            *(float2*)(ob1 + 8 * j) = o1;
        }
    }
}

// ---------------------------------------------------------------------------
extern "C" void kernel_launch(void* const* d_in, const int* in_sizes, int n_in,
                              void* d_out, int out_size)
{
    const float* ll     = (const float*)d_in[0];   // (16,1024,64,1)
    const float* logits = (const float*)d_in[1];   // (64,64,4,4,1)
    float* out          = (float*)d_out;           // (16,1024,64,1)

    sumconv_fused_kernel<<<512, 256>>>(ll, logits, out);
}

// round 7
// speedup vs baseline: 1.2384x; 1.2384x over previous
#include <cuda_runtime.h>
#include <cuda_bf16.h>
#include <cstdint>
#include <cstring>

// ============================================================================
// SumConv via mma.sync (HMMA, compute_103-safe), two kernels + PDL overlap.
//   out[b,f,co] = log( sum_ci exp(ll[b,f,ci]) * softmax_ci(logits)[co,ci,kh,kw] )
// Kernel 1 (primary): softmax weights -> bf16 hi/lo pre-swizzled SMEM images
//   g_wimg[g] = [Wh 8KB][Wl 8KB]; signals griddepcontrol.launch_dependents.
// Kernel 2 (secondary, ProgrammaticStreamSerialization): runs E-phase prologue
//   (DRAM loads + exp + bf16 split + A-tile stores) overlapped with kernel 1,
//   then griddepcontrol.wait -> copy W image -> 3-term bf16 split GEMM
//   (Eh*Wh + Eh*Wl + El*Wh) fp32 accum -> log -> store.
// ============================================================================

#define SWZ(x) ((x) ^ (((x) >> 3) & 0x70))

__device__ __forceinline__ uint32_t smem_u32(const void* p) {
    uint32_t a;
    asm("{ .reg .u64 t; cvta.to.shared.u64 t, %1; cvt.u32.u64 %0, t; }" : "=r"(a) : "l"(p));
    return a;
}

#define LDSM_X4(r0, r1, r2, r3, addr) \
    asm volatile("ldmatrix.sync.aligned.m8n8.x4.shared.b16 {%0,%1,%2,%3}, [%4];" \
        : "=r"(r0), "=r"(r1), "=r"(r2), "=r"(r3) : "r"(addr))

#define MMA_BF16(D, A, B0, B1) \
    asm volatile("mma.sync.aligned.m16n8k16.row.col.f32.bf16.bf16.f32 " \
        "{%0,%1,%2,%3}, {%4,%5,%6,%7}, {%8,%9}, {%0,%1,%2,%3};" \
        : "+f"(D[0]), "+f"(D[1]), "+f"(D[2]), "+f"(D[3]) \
        : "r"(A[0]), "r"(A[1]), "r"(A[2]), "r"(A[3]), "r"(B0), "r"(B1))

// Pre-swizzled weight images: per group, [0,8K) = Wh, [8K,16K) = Wl.
__device__ __align__(16) unsigned char g_wimg[16][16384];

// ---------------------------------------------------------------------------
// Kernel 1: per-co softmax over ci for all 16 groups. Block = co (64 blocks).
// Thread t: float4 load covers ci = t>>2, groups 4*(t&3)..+3 (fully coalesced).
// ---------------------------------------------------------------------------
__global__ __launch_bounds__(256) void weights_kernel(const float* __restrict__ logits)
{
    __shared__ float red[8][16];
    __shared__ float sinv[16];
    const int t = threadIdx.x, l = t & 31, w = t >> 5;
    const int co = blockIdx.x;
    const int ci = t >> 2;
    const int qb = (t & 3) << 2;

    float4 v = *(const float4*)(logits + co * 1024 + 4 * t);
    float e0 = __expf(v.x), e1 = __expf(v.y), e2 = __expf(v.z), e3 = __expf(v.w);

    // reduce over the 8 lanes sharing (l&3): those cover 8 distinct ci
    float p0 = e0, p1 = e1, p2 = e2, p3 = e3;
    #pragma unroll
    for (int off = 4; off <= 16; off <<= 1) {
        p0 += __shfl_xor_sync(0xFFFFFFFFu, p0, off);
        p1 += __shfl_xor_sync(0xFFFFFFFFu, p1, off);
        p2 += __shfl_xor_sync(0xFFFFFFFFu, p2, off);
        p3 += __shfl_xor_sync(0xFFFFFFFFu, p3, off);
    }
    if (l < 4) {
        red[w][qb + 0] = p0; red[w][qb + 1] = p1;
        red[w][qb + 2] = p2; red[w][qb + 3] = p3;
    }
    __syncthreads();
    if (t < 16) {
        float s = 0.0f;
        #pragma unroll
        for (int ww = 0; ww < 8; ww++) s += red[ww][t];
        sinv[t] = __frcp_rn(s);
    }
    __syncthreads();

    const float wv[4] = { e0 * sinv[qb + 0], e1 * sinv[qb + 1],
                          e2 * sinv[qb + 2], e3 * sinv[qb + 3] };
    const bool even = ((ci & 1) == 0);     // lane l^4 holds ci^1, same qb
    #pragma unroll
    for (int j = 0; j < 4; j++) {
        float wj = wv[j];
        __nv_bfloat16 hb = __float2bfloat16(wj);
        __nv_bfloat16 lb = __float2bfloat16(wj - __bfloat162float(hb));
        unsigned short hu, lu; memcpy(&hu, &hb, 2); memcpy(&lu, &lb, 2);
        unsigned int hpart = __shfl_xor_sync(0xFFFFFFFFu, (unsigned int)hu, 4);
        unsigned int lpart = __shfl_xor_sync(0xFFFFFFFFu, (unsigned int)lu, 4);
        if (even) {
            unsigned int hv = (unsigned int)hu | (hpart << 16);
            unsigned int lv = (unsigned int)lu | (lpart << 16);
            int g = qb + j;
            uint32_t off = SWZ((uint32_t)(co * 128 + ci * 2));   // 4B-aligned (ci even)
            *(unsigned int*)(g_wimg[g] + off)        = hv;
            *(unsigned int*)(g_wimg[g] + 8192 + off) = lv;
        }
    }
    // allow the dependent grid to launch; its griddepcontrol.wait guarantees
    // visibility of the stores above.
    asm volatile("griddepcontrol.launch_dependents;" ::: "memory");
}

// ---------------------------------------------------------------------------
// Kernel 2: main GEMM+log. SMEM: Eh 4K | El 4K | Wh 8K | Wl 8K.
// ---------------------------------------------------------------------------
static constexpr int S_AH = 0;
static constexpr int S_AL = 4096;
static constexpr int S_BH = 8192;
static constexpr int S_BL = 16384;

__global__ __launch_bounds__(256) void sumconv_mma_kernel(
    const float* __restrict__ ll, float* __restrict__ out)
{
    __shared__ __align__(1024) unsigned char sm[24576];
    const uint32_t sa = smem_u32(sm);

    const int t   = threadIdx.x;
    const int wid = t >> 5;
    const int lid = t & 31;

    const int g    = blockIdx.x >> 5;    // group = kh*4 + kw
    const int tile = blockIdx.x & 31;    // 32-row M tile
    const int kh = g >> 2, kw = g & 3;
    const int fbase = kh * 32 + kw;

    // ---- Prologue (independent of weights): E loads, exp, split, A stores ----
    float4 v[2];
    int er[2], ec4[2];
    #pragma unroll
    for (int i = 0; i < 2; i++) {
        int idx4 = t + 256 * i;          // 0..511
        int r    = idx4 >> 4;            // local row 0..31
        int c4   = (idx4 & 15) << 2;
        er[i] = r; ec4[i] = c4;
        int ridx = tile * 32 + r;
        int b    = ridx >> 6;
        int pos  = ridx & 63;
        int f    = ((pos >> 3) << 7) + ((pos & 7) << 2) + fbase;
        v[i] = *(const float4*)(ll + ((((b << 10) + f) << 6) + c4));
    }

    #pragma unroll
    for (int i = 0; i < 2; i++) {
        float e0 = __expf(v[i].x), e1 = __expf(v[i].y);
        float e2 = __expf(v[i].z), e3 = __expf(v[i].w);
        __nv_bfloat16 h0 = __float2bfloat16(e0), h1 = __float2bfloat16(e1);
        __nv_bfloat16 h2 = __float2bfloat16(e2), h3 = __float2bfloat16(e3);
        __nv_bfloat16 q0 = __float2bfloat16(e0 - __bfloat162float(h0));
        __nv_bfloat16 q1 = __float2bfloat16(e1 - __bfloat162float(h1));
        __nv_bfloat16 q2 = __float2bfloat16(e2 - __bfloat162float(h2));
        __nv_bfloat16 q3 = __float2bfloat16(e3 - __bfloat162float(h3));
        unsigned long long uh, ul;
        {
            unsigned short s0, s1, s2, s3;
            memcpy(&s0, &h0, 2); memcpy(&s1, &h1, 2); memcpy(&s2, &h2, 2); memcpy(&s3, &h3, 2);
            uh = (unsigned long long)s0 | ((unsigned long long)s1 << 16) |
                 ((unsigned long long)s2 << 32) | ((unsigned long long)s3 << 48);
            memcpy(&s0, &q0, 2); memcpy(&s1, &q1, 2); memcpy(&s2, &q2, 2); memcpy(&s3, &q3, 2);
            ul = (unsigned long long)s0 | ((unsigned long long)s1 << 16) |
                 ((unsigned long long)s2 << 32) | ((unsigned long long)s3 << 48);
        }
        uint32_t sw = SWZ((uint32_t)(er[i] * 128 + ec4[i] * 2));
        *(unsigned long long*)(sm + S_AH + sw) = uh;
        *(unsigned long long*)(sm + S_AL + sw) = ul;
    }

    // ---- Wait for weights kernel's memory, then copy pre-swizzled image ----
    asm volatile("griddepcontrol.wait;" ::: "memory");
    #pragma unroll
    for (int i = 0; i < 4; i++) {
        float4 wv = *(const float4*)(g_wimg[g] + 16 * t + 4096 * i);
        *(float4*)(sm + S_BH + 16 * t + 4096 * i) = wv;
    }

    __syncthreads();

    // ---- MMA: warp -> m16 (rows 16*(wid&1)) x n16 (cols 16*(wid>>1)) ----
    const int mrow  = 16 * (wid & 1);
    const int nbase = 16 * (wid >> 1);

    const uint32_t a_row = mrow + (lid & 7) + ((lid >> 3) & 1) * 8;
    const uint32_t a_kb  = ((lid >> 4) & 1) * 16;
    const uint32_t b_row = nbase + (lid & 7) + ((lid >> 4) & 1) * 8;
    const uint32_t b_kb  = ((lid >> 3) & 1) * 16;

    float acc[2][4];
    #pragma unroll
    for (int j = 0; j < 2; j++)
        #pragma unroll
        for (int q = 0; q < 4; q++) acc[j][q] = 0.0f;

    #pragma unroll
    for (int kc = 0; kc < 4; kc++) {
        uint32_t ah[4], al[4], bh[4], bl[4];
        uint32_t aoff = SWZ(a_row * 128 + kc * 32 + a_kb);
        uint32_t boff = SWZ(b_row * 128 + kc * 32 + b_kb);
        LDSM_X4(ah[0], ah[1], ah[2], ah[3], sa + S_AH + aoff);
        LDSM_X4(al[0], al[1], al[2], al[3], sa + S_AL + aoff);
        LDSM_X4(bh[0], bh[1], bh[2], bh[3], sa + S_BH + boff);
        LDSM_X4(bl[0], bl[1], bl[2], bl[3], sa + S_BL + boff);

        MMA_BF16(acc[0], ah, bh[0], bh[1]);
        MMA_BF16(acc[1], ah, bh[2], bh[3]);
        MMA_BF16(acc[0], al, bh[0], bh[1]);
        MMA_BF16(acc[1], al, bh[2], bh[3]);
        MMA_BF16(acc[0], ah, bl[0], bl[1]);
        MMA_BF16(acc[1], ah, bl[2], bl[3]);
    }

    // ---- Epilogue: log + store ----
    {
        int r0 = mrow + (lid >> 2);
        int r1 = r0 + 8;
        int cb = nbase + 2 * (lid & 3);

        int ridx0 = tile * 32 + r0;
        int b0 = ridx0 >> 6, p0 = ridx0 & 63;
        int f0 = ((p0 >> 3) << 7) + ((p0 & 7) << 2) + fbase;
        float* ob0 = out + ((((b0 << 10) + f0) << 6) + cb);

        int ridx1 = tile * 32 + r1;
        int b1 = ridx1 >> 6, p1 = ridx1 & 63;
        int f1 = ((p1 >> 3) << 7) + ((p1 & 7) << 2) + fbase;
        float* ob1 = out + ((((b1 << 10) + f1) << 6) + cb);

        #pragma unroll
        for (int j = 0; j < 2; j++) {
            float2 o0, o1;
            o0.x = __logf(acc[j][0]);
            o0.y = __logf(acc[j][1]);
            o1.x = __logf(acc[j][2]);
            o1.y = __logf(acc[j][3]);
            *(float2*)(ob0 + 8 * j) = o0;
            *(float2*)(ob1 + 8 * j) = o1;
        }
    }
}

// ---------------------------------------------------------------------------
extern "C" void kernel_launch(void* const* d_in, const int* in_sizes, int n_in,
                              void* d_out, int out_size)
{
    const float* ll     = (const float*)d_in[0];   // (16,1024,64,1)
    const float* logits = (const float*)d_in[1];   // (64,64,4,4,1)
    float* out          = (float*)d_out;           // (16,1024,64,1)

    weights_kernel<<<64, 256>>>(logits);

    // Secondary launch with programmatic stream serialization: may start as
    // soon as weights_kernel signals launch_dependents; griddepcontrol.wait
    // inside the kernel provides the memory ordering.
    cudaLaunchConfig_t cfg = {};
    cfg.gridDim  = dim3(512, 1, 1);
    cfg.blockDim = dim3(256, 1, 1);
    cfg.dynamicSmemBytes = 0;
    cfg.stream = (cudaStream_t)0;   // legacy default stream (same as <<<>>>)
    cudaLaunchAttribute attr;
    attr.id = cudaLaunchAttributeProgrammaticStreamSerialization;
    attr.val.programmaticStreamSerializationAllowed = 1;
    cfg.attrs = &attr;
    cfg.numAttrs = 1;
    cudaLaunchKernelEx(&cfg, sumconv_mma_kernel, ll, out);
}

// round 8
// speedup vs baseline: 1.4760x; 1.1919x over previous
#include <cuda_runtime.h>
#include <cuda_bf16.h>
#include <cstdint>
#include <cstring>

// ============================================================================
// SumConv via mma.sync (HMMA, compute_103-safe), two kernels + PDL overlap.
//   out[b,f,co] = log( sum_ci exp(ll[b,f,ci]) * softmax_ci(logits)[co,ci,kh,kw] )
// Kernel 1 (primary): softmax weights -> bf16 hi/lo pre-swizzled SMEM images
//   g_wimg[g] = [Wh 8KB][Wl 8KB]; signals griddepcontrol.launch_dependents.
// Kernel 2 (secondary, PDL): E-phase prologue (DRAM loads + exp + bf16x2 split
//   + A-tile stores) overlapped with kernel 1 / the wait stall, then
//   griddepcontrol.wait -> cp.async W image -> 3-term bf16 split GEMM
//   (Eh*Wh + Eh*Wl + El*Wh) fp32 accum -> log -> store.
// ============================================================================

#define SWZ(x) ((x) ^ (((x) >> 3) & 0x70))

__device__ __forceinline__ uint32_t smem_u32(const void* p) {
    uint32_t a;
    asm("{ .reg .u64 t; cvta.to.shared.u64 t, %1; cvt.u32.u64 %0, t; }" : "=r"(a) : "l"(p));
    return a;
}

// d = { bf16(hi) , bf16(lo) }  (hi -> upper 16 bits)
__device__ __forceinline__ uint32_t cvt_bf16x2(float hi, float lo) {
    uint32_t r;
    asm("cvt.rn.bf16x2.f32 %0, %1, %2;" : "=r"(r) : "f"(hi), "f"(lo));
    return r;
}

#define LDSM_X4(r0, r1, r2, r3, addr) \
    asm volatile("ldmatrix.sync.aligned.m8n8.x4.shared.b16 {%0,%1,%2,%3}, [%4];" \
        : "=r"(r0), "=r"(r1), "=r"(r2), "=r"(r3) : "r"(addr))

#define MMA_BF16(D, A, B0, B1) \
    asm volatile("mma.sync.aligned.m16n8k16.row.col.f32.bf16.bf16.f32 " \
        "{%0,%1,%2,%3}, {%4,%5,%6,%7}, {%8,%9}, {%0,%1,%2,%3};" \
        : "+f"(D[0]), "+f"(D[1]), "+f"(D[2]), "+f"(D[3]) \
        : "r"(A[0]), "r"(A[1]), "r"(A[2]), "r"(A[3]), "r"(B0), "r"(B1))

// Pre-swizzled weight images: per group, [0,8K) = Wh, [8K,16K) = Wl.
__device__ __align__(16) unsigned char g_wimg[16][16384];

// ---------------------------------------------------------------------------
// Kernel 1: per-co softmax over ci for all 16 groups. Block = co (64 blocks).
// Thread t: float4 load covers ci = t>>2, groups 4*(t&3)..+3 (fully coalesced).
// ---------------------------------------------------------------------------
__global__ __launch_bounds__(256) void weights_kernel(const float* __restrict__ logits)
{
    __shared__ float red[8][16];
    __shared__ float sinv[16];
    const int t = threadIdx.x, l = t & 31, w = t >> 5;
    const int co = blockIdx.x;
    const int ci = t >> 2;
    const int qb = (t & 3) << 2;

    float4 v = *(const float4*)(logits + co * 1024 + 4 * t);
    float e0 = __expf(v.x), e1 = __expf(v.y), e2 = __expf(v.z), e3 = __expf(v.w);

    // reduce over the 8 lanes sharing (l&3): those cover 8 distinct ci
    float p0 = e0, p1 = e1, p2 = e2, p3 = e3;
    #pragma unroll
    for (int off = 4; off <= 16; off <<= 1) {
        p0 += __shfl_xor_sync(0xFFFFFFFFu, p0, off);
        p1 += __shfl_xor_sync(0xFFFFFFFFu, p1, off);
        p2 += __shfl_xor_sync(0xFFFFFFFFu, p2, off);
        p3 += __shfl_xor_sync(0xFFFFFFFFu, p3, off);
    }
    if (l < 4) {
        red[w][qb + 0] = p0; red[w][qb + 1] = p1;
        red[w][qb + 2] = p2; red[w][qb + 3] = p3;
    }
    __syncthreads();
    if (t < 16) {
        float s = 0.0f;
        #pragma unroll
        for (int ww = 0; ww < 8; ww++) s += red[ww][t];
        sinv[t] = __frcp_rn(s);
    }
    __syncthreads();

    const float wv[4] = { e0 * sinv[qb + 0], e1 * sinv[qb + 1],
                          e2 * sinv[qb + 2], e3 * sinv[qb + 3] };
    const bool even = ((ci & 1) == 0);     // lane l^4 holds ci^1, same qb
    #pragma unroll
    for (int j = 0; j < 4; j++) {
        float wj = wv[j];
        __nv_bfloat16 hb = __float2bfloat16(wj);
        __nv_bfloat16 lb = __float2bfloat16(wj - __bfloat162float(hb));
        unsigned short hu, lu; memcpy(&hu, &hb, 2); memcpy(&lu, &lb, 2);
        unsigned int hpart = __shfl_xor_sync(0xFFFFFFFFu, (unsigned int)hu, 4);
        unsigned int lpart = __shfl_xor_sync(0xFFFFFFFFu, (unsigned int)lu, 4);
        if (even) {
            unsigned int hv = (unsigned int)hu | (hpart << 16);
            unsigned int lv = (unsigned int)lu | (lpart << 16);
            int g = qb + j;
            uint32_t off = SWZ((uint32_t)(co * 128 + ci * 2));   // 4B-aligned (ci even)
            *(unsigned int*)(g_wimg[g] + off)        = hv;
            *(unsigned int*)(g_wimg[g] + 8192 + off) = lv;
        }
    }
    // allow the dependent grid to proceed past its wait; all stores above
    // are guaranteed visible to it.
    asm volatile("griddepcontrol.launch_dependents;" ::: "memory");
}

// ---------------------------------------------------------------------------
// Kernel 2: main GEMM+log. SMEM: Eh 4K | El 4K | Wh 8K | Wl 8K.
// ---------------------------------------------------------------------------
static constexpr int S_AH = 0;
static constexpr int S_AL = 4096;
static constexpr int S_BH = 8192;
static constexpr int S_BL = 16384;

__global__ __launch_bounds__(256) void sumconv_mma_kernel(
    const float* __restrict__ ll, float* __restrict__ out)
{
    __shared__ __align__(1024) unsigned char sm[24576];
    const uint32_t sa = smem_u32(sm);

    const int t   = threadIdx.x;
    const int wid = t >> 5;
    const int lid = t & 31;

    const int g    = blockIdx.x >> 5;    // group = kh*4 + kw
    const int tile = blockIdx.x & 31;    // 32-row M tile
    const int kh = g >> 2, kw = g & 3;
    const int fbase = kh * 32 + kw;

    // ---- Prologue (independent of weights): E loads, exp, split, A stores ----
    float4 v[2];
    int er[2], ec4[2];
    #pragma unroll
    for (int i = 0; i < 2; i++) {
        int idx4 = t + 256 * i;          // 0..511
        int r    = idx4 >> 4;            // local row 0..31
        int c4   = (idx4 & 15) << 2;
        er[i] = r; ec4[i] = c4;
        int ridx = tile * 32 + r;
        int b    = ridx >> 6;
        int pos  = ridx & 63;
        int f    = ((pos >> 3) << 7) + ((pos & 7) << 2) + fbase;
        v[i] = *(const float4*)(ll + ((((b << 10) + f) << 6) + c4));
    }

    #pragma unroll
    for (int i = 0; i < 2; i++) {
        float e0 = __expf(v[i].x), e1 = __expf(v[i].y);
        float e2 = __expf(v[i].z), e3 = __expf(v[i].w);

        // hi pack: {e1,e0} and {e3,e2}, low element in low 16 bits
        uint32_t h01 = cvt_bf16x2(e1, e0);
        uint32_t h23 = cvt_bf16x2(e3, e2);
        // lo = e - float(bf16_hi): bf16 -> f32 is a 16-bit shift
        float hf0 = __uint_as_float(h01 << 16);
        float hf1 = __uint_as_float(h01 & 0xFFFF0000u);
        float hf2 = __uint_as_float(h23 << 16);
        float hf3 = __uint_as_float(h23 & 0xFFFF0000u);
        uint32_t l01 = cvt_bf16x2(e1 - hf1, e0 - hf0);
        uint32_t l23 = cvt_bf16x2(e3 - hf3, e2 - hf2);

        unsigned long long uh =
            (unsigned long long)h01 | ((unsigned long long)h23 << 32);
        unsigned long long ul =
            (unsigned long long)l01 | ((unsigned long long)l23 << 32);

        uint32_t sw = SWZ((uint32_t)(er[i] * 128 + ec4[i] * 2));
        *(unsigned long long*)(sm + S_AH + sw) = uh;
        *(unsigned long long*)(sm + S_AL + sw) = ul;
    }

    // ---- Wait for weights kernel memory, then async-copy the W image ----
    asm volatile("griddepcontrol.wait;" ::: "memory");
    {
        const char* wg = (const char*)(g_wimg[g]) + 16 * t;
        #pragma unroll
        for (int i = 0; i < 4; i++) {
            asm volatile("cp.async.cg.shared.global [%0], [%1], 16;"
                         :: "r"(sa + S_BH + 16 * t + 4096 * i),
                            "l"(wg + 4096 * i) : "memory");
        }
        asm volatile("cp.async.commit_group;" ::: "memory");
        asm volatile("cp.async.wait_group 0;" ::: "memory");
    }
    __syncthreads();

    // ---- MMA: warp -> m16 (rows 16*(wid&1)) x n16 (cols 16*(wid>>1)) ----
    const int mrow  = 16 * (wid & 1);
    const int nbase = 16 * (wid >> 1);

    const uint32_t a_row = mrow + (lid & 7) + ((lid >> 3) & 1) * 8;
    const uint32_t a_kb  = ((lid >> 4) & 1) * 16;
    const uint32_t b_row = nbase + (lid & 7) + ((lid >> 4) & 1) * 8;
    const uint32_t b_kb  = ((lid >> 3) & 1) * 16;

    float acc[2][4];
    #pragma unroll
    for (int j = 0; j < 2; j++)
        #pragma unroll
        for (int q = 0; q < 4; q++) acc[j][q] = 0.0f;

    #pragma unroll
    for (int kc = 0; kc < 4; kc++) {
        uint32_t ah[4], al[4], bh[4], bl[4];
        uint32_t aoff = SWZ(a_row * 128 + kc * 32 + a_kb);
        uint32_t boff = SWZ(b_row * 128 + kc * 32 + b_kb);
        LDSM_X4(ah[0], ah[1], ah[2], ah[3], sa + S_AH + aoff);
        LDSM_X4(al[0], al[1], al[2], al[3], sa + S_AL + aoff);
        LDSM_X4(bh[0], bh[1], bh[2], bh[3], sa + S_BH + boff);
        LDSM_X4(bl[0], bl[1], bl[2], bl[3], sa + S_BL + boff);

        MMA_BF16(acc[0], ah, bh[0], bh[1]);
        MMA_BF16(acc[1], ah, bh[2], bh[3]);
        MMA_BF16(acc[0], al, bh[0], bh[1]);
        MMA_BF16(acc[1], al, bh[2], bh[3]);
        MMA_BF16(acc[0], ah, bl[0], bl[1]);
        MMA_BF16(acc[1], ah, bl[2], bl[3]);
    }

    // ---- Epilogue: log + store ----
    {
        int r0 = mrow + (lid >> 2);
        int r1 = r0 + 8;
        int cb = nbase + 2 * (lid & 3);

        int ridx0 = tile * 32 + r0;
        int b0 = ridx0 >> 6, p0 = ridx0 & 63;
        int f0 = ((p0 >> 3) << 7) + ((p0 & 7) << 2) + fbase;
        float* ob0 = out + ((((b0 << 10) + f0) << 6) + cb);

        int ridx1 = tile * 32 + r1;
        int b1 = ridx1 >> 6, p1 = ridx1 & 63;
        int f1 = ((p1 >> 3) << 7) + ((p1 & 7) << 2) + fbase;
        float* ob1 = out + ((((b1 << 10) + f1) << 6) + cb);

        #pragma unroll
        for (int j = 0; j < 2; j++) {
            float2 o0, o1;
            o0.x = __logf(acc[j][0]);
            o0.y = __logf(acc[j][1]);
            o1.x = __logf(acc[j][2]);
            o1.y = __logf(acc[j][3]);
            *(float2*)(ob0 + 8 * j) = o0;
            *(float2*)(ob1 + 8 * j) = o1;
        }
    }
}

// ---------------------------------------------------------------------------
extern "C" void kernel_launch(void* const* d_in, const int* in_sizes, int n_in,
                              void* d_out, int out_size)
{
    const float* ll     = (const float*)d_in[0];   // (16,1024,64,1)
    const float* logits = (const float*)d_in[1];   // (64,64,4,4,1)
    float* out          = (float*)d_out;           // (16,1024,64,1)

    weights_kernel<<<64, 256>>>(logits);

    // Secondary launch with programmatic stream serialization: may start as
    // soon as weights_kernel signals launch_dependents; griddepcontrol.wait
    // inside the kernel provides the memory ordering.
    cudaLaunchConfig_t cfg = {};
    cfg.gridDim  = dim3(512, 1, 1);
    cfg.blockDim = dim3(256, 1, 1);
    cfg.dynamicSmemBytes = 0;
    cfg.stream = (cudaStream_t)0;   // legacy default stream (same as <<<>>>)
    cudaLaunchAttribute attr;
    attr.id = cudaLaunchAttributeProgrammaticStreamSerialization;
    attr.val.programmaticStreamSerializationAllowed = 1;
    cfg.attrs = &attr;
    cfg.numAttrs = 1;
    cudaLaunchKernelEx(&cfg, sumconv_mma_kernel, ll, out);
}